// round 13
// baseline (speedup 1.0000x reference)
#include <cuda_runtime.h>
#include <cuda_fp16.h>

#define TT 256
typedef unsigned int u32; typedef unsigned long long u64; typedef unsigned short u16;

// [mat 0..3][ih 0..1][p 0..3][kk 0..63][u 0..31][gate 0..3] half2(w_2kk, w_2kk+1)
__device__ __align__(16) __half2 g_W[262144];
__device__ __align__(16) __half2 g_OWp[8192];    // [p][kk][u]
__device__ float g_b[4][512];

__global__ void prep_kernel(
    const float* __restrict__ eW0, const float* __restrict__ eU0,
    const float* __restrict__ ebi0, const float* __restrict__ ebh0,
    const float* __restrict__ eW1, const float* __restrict__ eU1,
    const float* __restrict__ ebi1, const float* __restrict__ ebh1,
    const float* __restrict__ dW0, const float* __restrict__ dU0,
    const float* __restrict__ dbi0, const float* __restrict__ dbh0,
    const float* __restrict__ dW1, const float* __restrict__ dU1,
    const float* __restrict__ dbi1, const float* __restrict__ dbh1,
    const float* __restrict__ oW)
{
    int idx = blockIdx.x * 512 + threadIdx.x;
    int g = idx & 3, u = (idx >> 2) & 31, kk = (idx >> 7) & 63;
    int p = (idx >> 13) & 3, ih = (idx >> 15) & 1, mat = (idx >> 16) & 3;
    int sel = mat * 2 + ih;
    const float* M = (sel==0)?eW0:(sel==1)?eU0:(sel==2)?eW1:(sel==3)?eU1:
                     (sel==4)?dW0:(sel==5)?dU0:(sel==6)?dW1:dU1;
    int j = g * 128 + p * 32 + u;
    g_W[idx] = __floats2half2_rn(M[j*128 + 2*kk], M[j*128 + 2*kk + 1]);
    if (idx < 8192) {
        int d = (idx >> 11) * 32 + (idx & 31);
        int k2 = (idx >> 5) & 63;
        g_OWp[idx] = __floats2half2_rn(oW[d*128 + 2*k2], oW[d*128 + 2*k2 + 1]);
    }
    if (idx < 512) {
        g_b[0][idx] = ebi0[idx] + ebh0[idx];
        g_b[1][idx] = ebi1[idx] + ebh1[idx];
        g_b[2][idx] = dbi0[idx] + dbh0[idx];
        g_b[3][idx] = dbi1[idx] + dbh1[idx];
    }
}

__device__ __forceinline__ float sigf(float v)   { return 1.0f / (1.0f + __expf(-v)); }
__device__ __forceinline__ float tanhfa(float v) { return 1.0f - 2.0f / (__expf(2.0f * v) + 1.0f); }
__device__ __forceinline__ __half2 h2(u32 v) { return *(__half2*)&v; }
__device__ __forceinline__ u32 pk(float a, float b) {
    __half2 h = __floats2half2_rn(a, b); return *(u32*)&h;
}
__device__ __forceinline__ void spill(u64& acc, __half2 a) {
    float lo = __low2float(a), hi = __high2float(a);
    u64 q;
    asm("mov.b64 %0, {%1,%2};" : "=l"(q) : "f"(lo), "f"(hi));
    asm("add.rn.f32x2 %0, %1, %2;" : "=l"(acc) : "l"(acc), "l"(q));
}
__device__ __forceinline__ float fin2(u64 acc) {
    float lo, hi;
    asm("mov.b64 {%0,%1}, %2;" : "=f"(lo), "=f"(hi) : "l"(acc));
    return lo + hi;
}

// xh buffers: 4KB per parity, packed [sk(4)][rq(4)][kkl(16)][r4(4)] half2
__device__ __forceinline__ u32 xh_word(int k, int row) {
    int kk = k >> 1;
    return (u32)(((((kk >> 4) * 4 + (row >> 2)) * 16 + (kk & 15)) * 4) + (row & 3));
}
// byte offset of h(row 0..15, global unit uu 0..127) inside an xh buffer
__device__ __forceinline__ u32 hboff(int row, int uu) {
    return (u32)(((((uu >> 5) * 4 + (row >> 2)) * 16 + ((uu >> 1) & 15)) * 4 + (row & 3)) * 4
                 + ((uu & 1) << 1));
}

#define SW0I 0u
#define SW0H 32768u
#define SW1I 65536u
#define SW1H 98304u
#define SX   131072u
#define SH0  139264u
#define SH1  147456u
#define SOW  155648u
#define SMB  163840u    // mbarriers: B0[g] at g*16, B1[g] at g*16+8
#define SRED0 164864u   // [s][gate][row16][u] float = 32KB
#define SRED1 197632u
#define STOT  230400

#define CBAR() do { asm volatile("barrier.cluster.arrive.aligned;" ::: "memory"); \
                    asm volatile("barrier.cluster.wait.aligned;"   ::: "memory"); } while (0)
#define BARG() asm volatile("bar.sync %0, 256;" :: "r"(g + 1) : "memory")

#define MBAR_WAIT(addr, parity) do { u32 _d = 0; \
    while (!_d) { \
        asm volatile("{.reg .pred p; mbarrier.try_wait.parity.acquire.cluster.shared::cta.b64 p, [%1], %2, 0x989680; selp.b32 %0,1,0,p;}" \
                     : "=r"(_d) : "r"(addr), "r"(parity) : "memory"); \
    } } while (0)

__device__ __forceinline__ void arrive4(const u32* am) {
#pragma unroll
    for (int r = 0; r < 4; r++)
        asm volatile("mbarrier.arrive.release.cluster.shared::cluster.b64 _, [%0];"
                     :: "r"(am[r]) : "memory");
}
__device__ __forceinline__ void bc4(const u32* dsm, u32 off, u16 v) {
#pragma unroll
    for (int r = 0; r < 4; r++)
        asm volatile("st.shared::cluster.u16 [%0], %1;"
                     :: "r"(dsm[r] + off), "h"(v) : "memory");
}

__device__ __forceinline__ void stage_w(char* sm, int mat, int p, int tid) {
    const uint4* s0 = (const uint4*)g_W + ((mat*2+0)*4 + p) * 2048;
    const uint4* s1 = (const uint4*)g_W + ((mat*2+1)*4 + p) * 2048;
    uint4* d0 = (uint4*)(sm + (mat & 1) * 65536);
    uint4* d1 = (uint4*)(sm + (mat & 1) * 65536 + 32768);
#pragma unroll
    for (int i = 0; i < 4; i++) {
        d0[tid + i*512] = s0[tid + i*512];
        d1[tid + i*512] = s1[tid + i*512];
    }
}

// 4 rows x 4 gates over k-quarter s. g16[gate*4 + r].
__device__ __forceinline__ void gemm_r4(const char* sm, u32 wI, u32 wH,
    u32 xo, u32 ho, int u, int rg, int s, float* g16)
{
    const uint4* wi = (const uint4*)(sm + wI) + s*512 + u;
    const uint4* wh = (const uint4*)(sm + wH) + s*512 + u;
    const uint4* xr = (const uint4*)(sm + xo) + (s*4 + rg)*16;
    const uint4* hr = (const uint4*)(sm + ho) + (s*4 + rg)*16;
    u64 A[16];
#pragma unroll
    for (int i = 0; i < 16; i++) A[i] = 0;
#pragma unroll
    for (int c = 0; c < 4; c++) {
        __half2 a[16];
#pragma unroll
        for (int i = 0; i < 16; i++) a[i] = __float2half2_rn(0.f);
#pragma unroll
        for (int m = 0; m < 4; m++) {
            int kkl = c*4 + m;
            uint4 wq = wi[kkl*32];
            uint4 vq = wh[kkl*32];
            uint4 xq = xr[kkl];
            uint4 hq = hr[kkl];
#pragma unroll
            for (int r = 0; r < 4; r++) {
                __half2 xv = ((__half2*)&xq)[r];
                __half2 hv = ((__half2*)&hq)[r];
                a[r]    = __hfma2(h2(wq.x), xv, a[r]);
                a[4+r]  = __hfma2(h2(wq.y), xv, a[4+r]);
                a[8+r]  = __hfma2(h2(wq.z), xv, a[8+r]);
                a[12+r] = __hfma2(h2(wq.w), xv, a[12+r]);
                a[r]    = __hfma2(h2(vq.x), hv, a[r]);
                a[4+r]  = __hfma2(h2(vq.y), hv, a[4+r]);
                a[8+r]  = __hfma2(h2(vq.z), hv, a[8+r]);
                a[12+r] = __hfma2(h2(vq.w), hv, a[12+r]);
            }
        }
#pragma unroll
        for (int i = 0; i < 16; i++) spill(A[i], a[i]);
    }
#pragma unroll
    for (int i = 0; i < 16; i++) g16[i] = fin2(A[i]);
}

__device__ __forceinline__ void red_store(char* sm, u32 base, int u, int rg, int s,
                                          const float* g16) {
    float* d = (float*)(sm + base) + u;
#pragma unroll
    for (int gate = 0; gate < 4; gate++)
#pragma unroll
        for (int r = 0; r < 4; r++)
            d[(((s*4 + gate) * 16) + rg*4 + r) * 32] = g16[gate*4 + r];
}

// epilogue: 4 cells (row16, units ub+8j). dst2off==0 -> no second store.
__device__ __forceinline__ void epi_layer(
    const char* sm, u32 redbase, u32 dstoff, u32 dst2off,
    const u32* dsm, int row16, int ub, int p,
    const float* bi, float* c)
{
#pragma unroll
    for (int j = 0; j < 4; j++) {
        int uu = ub + 8*j;
        const float* d = (const float*)(sm + redbase) + uu;
        float gt[4];
#pragma unroll
        for (int gate = 0; gate < 4; gate++) {
            gt[gate] = d[((0*4+gate)*16 + row16)*32] + d[((1*4+gate)*16 + row16)*32]
                     + d[((2*4+gate)*16 + row16)*32] + d[((3*4+gate)*16 + row16)*32]
                     + bi[gate*4 + j];
        }
        float cn = sigf(gt[1]) * c[j] + sigf(gt[0]) * tanhfa(gt[2]);
        c[j] = cn;
        float h = sigf(gt[3]) * tanhfa(cn);
        u16 hu = __half_as_ushort(__float2half(h));
        u32 ho = hboff(row16, p*32 + uu);
        bc4(dsm, dstoff + ho, hu);
        if (dst2off) bc4(dsm, dst2off + ho, hu);
    }
}

__global__ void __launch_bounds__(512, 1) __cluster_dims__(4, 1, 1)
lstm_main(const float* __restrict__ x, const float* __restrict__ out_b,
          float* __restrict__ out)
{
    extern __shared__ __align__(16) char sm[];
    const int tid = threadIdx.x;
    const int u = tid & 31, wid = tid >> 5;
    const int g = wid >> 3;              // group 0/1 (rows g*8..g*8+7)
    const int wl = wid & 7;              // warp in group
    const int s = wl >> 1, rg = g*2 + (wl & 1);
    const bool is_epi = (wl >= 6);
    const int p  = blockIdx.x & 3;
    const int bg = (blockIdx.x >> 2) * 16;

    u32 sb = (u32)__cvta_generic_to_shared(sm);
    u32 dsm[4], am0[4], am1[4];
    const u32 mb0 = sb + SMB + (u32)g*16, mb1 = mb0 + 8;
#pragma unroll
    for (int r = 0; r < 4; r++) {
        asm("mapa.shared::cluster.u32 %0, %1, %2;" : "=r"(dsm[r]) : "r"(sb), "r"(r));
        asm("mapa.shared::cluster.u32 %0, %1, %2;" : "=r"(am0[r]) : "r"(mb0), "r"(r));
        asm("mapa.shared::cluster.u32 %0, %1, %2;" : "=r"(am1[r]) : "r"(mb1), "r"(r));
    }
    if (tid == 0) {
#pragma unroll
        for (int b = 0; b < 4; b++)
            asm volatile("mbarrier.init.shared.b64 [%0], %1;"
                         :: "r"(sb + SMB + b*8), "r"(256) : "memory");
        asm volatile("fence.mbarrier_init.release.cluster;" ::: "memory");
    }

    stage_w(sm, 0, p, tid);
    stage_w(sm, 1, p, tid);
#pragma unroll
    for (int i = 0; i < 3; i++)
        ((uint4*)(sm + SX))[tid + i*512] = make_uint4(0,0,0,0);   // X,H0,H1
    __syncthreads();
    if (tid < 256) {
        const int xr = tid >> 4, oct = tid & 15;
        const float* xp = x + ((size_t)(bg + xr) * TT) * 128 + oct * 8;
        float4 a = *(const float4*)xp, b = *(const float4*)(xp + 4);
        u32* X = (u32*)(sm + SX);
        X[xh_word(oct*8+0, xr)] = pk(a.x, a.y);
        X[xh_word(oct*8+2, xr)] = pk(a.z, a.w);
        X[xh_word(oct*8+4, xr)] = pk(b.x, b.y);
        X[xh_word(oct*8+6, xr)] = pk(b.z, b.w);
    }
    // epilogue-thread state
    const int we = wl - 6;
    const int rloc = we*4 + (u >> 3), row16e = g*8 + rloc, ub = u & 7;
    float biA[16], biB[16], cc0[4] = {0,0,0,0}, cc1[4] = {0,0,0,0};
    if (is_epi) {
#pragma unroll
        for (int gate = 0; gate < 4; gate++)
#pragma unroll
            for (int j = 0; j < 4; j++) {
                biA[gate*4+j] = g_b[0][gate*128 + p*32 + ub + 8*j];
                biB[gate*4+j] = g_b[1][gate*128 + p*32 + ub + 8*j];
            }
    }
    float g16[16];
    int ph0 = 0, ph1 = 0;
    __syncthreads();
    CBAR();

    // ---------------- encoder: 1 mbarrier wait / step / group ----------------
    for (int t = 0; t < TT; t++) {
        const u32 pt = (u32)(t & 1) * 4096u, pn = pt ^ 4096u;
        float4 xa, xb;
        const bool xw = (wl < 4) && (t < TT - 1);
        if (xw) {
            const int xrow = g*8 + wl*2 + (u >> 4);
            const float* xp = x + ((size_t)(bg + xrow) * TT + t + 1) * 128 + (u & 15) * 8;
            xa = *(const float4*)xp; xb = *(const float4*)(xp + 4);
        }
        gemm_r4(sm, SW0I, SW0H, SX + pt, SH0 + pt, u, rg, s, g16);
        red_store(sm, SRED0, u, rg, s, g16);
        BARG();
        if (is_epi) {
            epi_layer(sm, SRED0, SH0 + pn, 0, dsm, row16e, ub, p, biA, cc0);
            arrive4(am0);
        } else if (xw) {
            const int xrow = g*8 + wl*2 + (u >> 4), oct = u & 15;
            u32* X = (u32*)(sm + SX + pn);
            X[xh_word(oct*8+0, xrow)] = pk(xa.x, xa.y);
            X[xh_word(oct*8+2, xrow)] = pk(xa.z, xa.w);
            X[xh_word(oct*8+4, xrow)] = pk(xb.x, xb.y);
            X[xh_word(oct*8+6, xrow)] = pk(xb.z, xb.w);
        }
        MBAR_WAIT(mb0, ph0); ph0 ^= 1;
        gemm_r4(sm, SW1I, SW1H, SH0 + pn, SH1 + pt, u, rg, s, g16);
        red_store(sm, SRED1, u, rg, s, g16);
        BARG();
        if (is_epi)   // H1 stores released by next step's B0 arrive (or switch CBAR)
            epi_layer(sm, SRED1, SH1 + pn, 0, dsm, row16e, ub, p, biB, cc1);
    }

    // ---------------- switch (groups converge) ----------------
    CBAR();
    if (tid < 256) {
        ((uint4*)(sm + SX))[tid]  = ((uint4*)(sm + SH1))[tid];  // x0 = final h1 (par 0)
        ((uint4*)(sm + SH0))[tid] = make_uint4(0,0,0,0);
        ((uint4*)(sm + SH1))[tid] = make_uint4(0,0,0,0);
    }
    stage_w(sm, 2, p, tid);
    stage_w(sm, 3, p, tid);
    ((uint4*)(sm + SOW))[tid] = ((const uint4*)g_OWp)[p * 512 + tid];
    if (is_epi) {
#pragma unroll
        for (int gate = 0; gate < 4; gate++)
#pragma unroll
            for (int j = 0; j < 4; j++) {
                biA[gate*4+j] = g_b[2][gate*128 + p*32 + ub + 8*j];
                biB[gate*4+j] = g_b[3][gate*128 + p*32 + ub + 8*j];
                cc0[j] = 0.f; cc1[j] = 0.f;
            }
    }
    const float obv = out_b[p * 32 + u];
    const int prow = g*8 + wl;
    const u32 pbase = (u32)((prow >> 2) * 256 + (prow & 3) * 4);
    __syncthreads();
    CBAR();

    // ---------------- decoder: 2 mbarrier waits / step / group ----------------
    for (int t = 0; t < TT; t++) {
        const u32 pt = (u32)(t & 1) * 4096u, pn = pt ^ 4096u;
        gemm_r4(sm, SW0I, SW0H, SX + pt, SH0 + pt, u, rg, s, g16);
        red_store(sm, SRED0, u, rg, s, g16);
        BARG();
        if (is_epi) {
            epi_layer(sm, SRED0, SH0 + pn, 0, dsm, row16e, ub, p, biA, cc0);
            arrive4(am0);
        }
        MBAR_WAIT(mb0, ph0); ph0 ^= 1;
        gemm_r4(sm, SW1I, SW1H, SH0 + pn, SH1 + pt, u, rg, s, g16);
        red_store(sm, SRED1, u, rg, s, g16);
        BARG();
        if (is_epi) {
            epi_layer(sm, SRED1, SH1 + pn, SX + pn, dsm, row16e, ub, p, biB, cc1);
            arrive4(am1);
        }
        MBAR_WAIT(mb1, ph1); ph1 ^= 1;
        {   // projection: warp -> row prow, lane -> dim p*32+u
            u64 P = 0;
            __half2 pa = __float2half2_rn(0.f);
            const char* hx = sm + SX + pn + pbase;
            const __half2* ow = (const __half2*)(sm + SOW) + u;
#pragma unroll 4
            for (int kk = 0; kk < 64; kk++) {
                __half2 hv = *(const __half2*)(hx + (kk >> 4)*1024 + (kk & 15)*16);
                pa = __hfma2(ow[kk*32], hv, pa);
                if ((kk & 15) == 15) { spill(P, pa); pa = __float2half2_rn(0.f); }
            }
            out[((size_t)(bg + prow) * TT + t) * 128 + p * 32 + u] = fin2(P) + obv;
        }
    }
    CBAR();
}

extern "C" void kernel_launch(void* const* d_in, const int* in_sizes, int n_in,
                              void* d_out, int out_size)
{
    cudaFuncSetAttribute(lstm_main, cudaFuncAttributeMaxDynamicSharedMemorySize, STOT);
    prep_kernel<<<512, 512>>>(
        (const float*)d_in[1],  (const float*)d_in[2],  (const float*)d_in[3],
        (const float*)d_in[4],  (const float*)d_in[5],  (const float*)d_in[6],
        (const float*)d_in[7],  (const float*)d_in[8],  (const float*)d_in[9],
        (const float*)d_in[10], (const float*)d_in[11], (const float*)d_in[12],
        (const float*)d_in[13], (const float*)d_in[14], (const float*)d_in[15],
        (const float*)d_in[16], (const float*)d_in[17]);
    lstm_main<<<128, 512, STOT>>>((const float*)d_in[0], (const float*)d_in[18],
                                  (float*)d_out);
}

// round 16
// speedup vs baseline: 1.1910x; 1.1910x over previous
#include <cuda_runtime.h>
#include <cuda_fp16.h>

#define TT 256
typedef unsigned int u32; typedef unsigned long long u64; typedef unsigned short u16;

// [mat 0..3][ih 0..1][p 0..3][kk 0..63][u 0..31][gate 0..3] half2(w_2kk, w_2kk+1)
__device__ __align__(16) __half2 g_W[262144];
__device__ __align__(16) __half2 g_OWp[8192];    // [p][kk][u]
__device__ float g_b[4][512];

__global__ void prep_kernel(
    const float* __restrict__ eW0, const float* __restrict__ eU0,
    const float* __restrict__ ebi0, const float* __restrict__ ebh0,
    const float* __restrict__ eW1, const float* __restrict__ eU1,
    const float* __restrict__ ebi1, const float* __restrict__ ebh1,
    const float* __restrict__ dW0, const float* __restrict__ dU0,
    const float* __restrict__ dbi0, const float* __restrict__ dbh0,
    const float* __restrict__ dW1, const float* __restrict__ dU1,
    const float* __restrict__ dbi1, const float* __restrict__ dbh1,
    const float* __restrict__ oW)
{
    int idx = blockIdx.x * 512 + threadIdx.x;
    int g = idx & 3, u = (idx >> 2) & 31, kk = (idx >> 7) & 63;
    int p = (idx >> 13) & 3, ih = (idx >> 15) & 1, mat = (idx >> 16) & 3;
    int sel = mat * 2 + ih;
    const float* M = (sel==0)?eW0:(sel==1)?eU0:(sel==2)?eW1:(sel==3)?eU1:
                     (sel==4)?dW0:(sel==5)?dU0:(sel==6)?dW1:dU1;
    int j = g * 128 + p * 32 + u;
    g_W[idx] = __floats2half2_rn(M[j*128 + 2*kk], M[j*128 + 2*kk + 1]);
    if (idx < 8192) {
        int d = (idx >> 11) * 32 + (idx & 31);
        int k2 = (idx >> 5) & 63;
        g_OWp[idx] = __floats2half2_rn(oW[d*128 + 2*k2], oW[d*128 + 2*k2 + 1]);
    }
    if (idx < 512) {
        g_b[0][idx] = ebi0[idx] + ebh0[idx];
        g_b[1][idx] = ebi1[idx] + ebh1[idx];
        g_b[2][idx] = dbi0[idx] + dbh0[idx];
        g_b[3][idx] = dbi1[idx] + dbh1[idx];
    }
}

__device__ __forceinline__ float sigf(float v)   { return 1.0f / (1.0f + __expf(-v)); }
__device__ __forceinline__ float tanhfa(float v) { return 1.0f - 2.0f / (__expf(2.0f * v) + 1.0f); }
__device__ __forceinline__ __half2 h2(u32 v) { return *(__half2*)&v; }
__device__ __forceinline__ u32 pk(float a, float b) {
    __half2 h = __floats2half2_rn(a, b); return *(u32*)&h;
}
__device__ __forceinline__ void spill(u64& acc, __half2 a) {
    float lo = __low2float(a), hi = __high2float(a);
    u64 q;
    asm("mov.b64 %0, {%1,%2};" : "=l"(q) : "f"(lo), "f"(hi));
    asm("add.rn.f32x2 %0, %1, %2;" : "=l"(acc) : "l"(acc), "l"(q));
}
__device__ __forceinline__ float fin2(u64 acc) {
    float lo, hi;
    asm("mov.b64 {%0,%1}, %2;" : "=f"(lo), "=f"(hi) : "l"(acc));
    return lo + hi;
}

// xh buffers: 4KB per parity. uint2 idx = ((kk>>4)*8 + (row>>1))*16 + (kk&15);
// uint2 = { half2(row even), half2(row odd) }.  u32 word = idx*2 + (row&1).
__device__ __forceinline__ u32 xh_word(int kk, int row) {
    return (u32)((((kk >> 4) * 8 + (row >> 1)) * 16 + (kk & 15)) * 2 + (row & 1));
}
// byte offset of h(row, dim uu 0..127)
__device__ __forceinline__ u32 hboff(int row, int uu) {
    return xh_word(uu >> 1, row) * 4 + ((u32)(uu & 1) << 1);
}

#define SW0I 0u
#define SW0H 32768u
#define SW1I 65536u
#define SW1H 98304u
#define SX   131072u
#define SH0  139264u
#define SH1  147456u
#define SOW  155648u
#define SRED0 163840u   // [s4][gate4][row16][u32] float = 32KB
#define SRED1 196608u   // 32KB
#define STOT  229376

#define CBAR() do { asm volatile("barrier.cluster.arrive.aligned;" ::: "memory"); \
                    asm volatile("barrier.cluster.wait.aligned;"   ::: "memory"); } while (0)

__device__ __forceinline__ void bc4(const u32* dsm, u32 off, u16 v) {
#pragma unroll
    for (int r = 0; r < 4; r++)
        asm volatile("st.shared::cluster.u16 [%0], %1;"
                     :: "r"(dsm[r] + off), "h"(v) : "memory");
}

__device__ __forceinline__ void stage_w(char* sm, int mat, int p, int tid) {
    const uint4* s0 = (const uint4*)g_W + ((mat*2+0)*4 + p) * 2048;
    const uint4* s1 = (const uint4*)g_W + ((mat*2+1)*4 + p) * 2048;
    uint4* d0 = (uint4*)(sm + (mat & 1) * 65536);
    uint4* d1 = (uint4*)(sm + (mat & 1) * 65536 + 32768);
#pragma unroll
    for (int i = 0; i < 2; i++) {
        d0[tid + i*1024] = s0[tid + i*1024];
        d1[tid + i*1024] = s1[tid + i*1024];
    }
}

// 2 rows x 4 gates over k-quarter s. g8[gate*2 + r].
__device__ __forceinline__ void gemm_r2(const char* sm, u32 wI, u32 wH,
    u32 xo, u32 ho, int u, int rp, int s, float* g8)
{
    const uint4* wi = (const uint4*)(sm + wI) + s*512 + u;
    const uint4* wh = (const uint4*)(sm + wH) + s*512 + u;
    const uint2* xr = (const uint2*)(sm + xo) + (s*8 + rp)*16;
    const uint2* hr = (const uint2*)(sm + ho) + (s*8 + rp)*16;
    u64 A[8];
#pragma unroll
    for (int i = 0; i < 8; i++) A[i] = 0;
#pragma unroll
    for (int c = 0; c < 4; c++) {
        __half2 a[8];
#pragma unroll
        for (int i = 0; i < 8; i++) a[i] = __float2half2_rn(0.f);
#pragma unroll
        for (int m = 0; m < 4; m++) {
            int kkl = c*4 + m;
            uint4 wq = wi[kkl*32];
            uint4 vq = wh[kkl*32];
            uint2 xq = xr[kkl];
            uint2 hq = hr[kkl];
#pragma unroll
            for (int r = 0; r < 2; r++) {
                __half2 xv = h2(r ? xq.y : xq.x);
                __half2 hv = h2(r ? hq.y : hq.x);
                a[r]   = __hfma2(h2(wq.x), xv, a[r]);
                a[2+r] = __hfma2(h2(wq.y), xv, a[2+r]);
                a[4+r] = __hfma2(h2(wq.z), xv, a[4+r]);
                a[6+r] = __hfma2(h2(wq.w), xv, a[6+r]);
                a[r]   = __hfma2(h2(vq.x), hv, a[r]);
                a[2+r] = __hfma2(h2(vq.y), hv, a[2+r]);
                a[4+r] = __hfma2(h2(vq.z), hv, a[4+r]);
                a[6+r] = __hfma2(h2(vq.w), hv, a[6+r]);
            }
        }
#pragma unroll
        for (int i = 0; i < 8; i++) spill(A[i], a[i]);
    }
#pragma unroll
    for (int i = 0; i < 8; i++) g8[i] = fin2(A[i]);
}

// store partials: SRED[s][gate][rp*2+r][u]  (max offset 32KB-4 < buffer size ✓)
__device__ __forceinline__ void red_store(char* sm, u32 base, int u, int rp, int s,
                                          const float* g8) {
    float* d = (float*)(sm + base) + u;
#pragma unroll
    for (int gate = 0; gate < 4; gate++)
#pragma unroll
        for (int r = 0; r < 2; r++)
            d[(((s*4 + gate) * 16) + rp*2 + r) * 32] = g8[gate*2 + r];
}
// thread (row, u): sum 4 k-slices per gate
__device__ __forceinline__ void red_gates(const char* sm, u32 base, int u, int row,
                                          float* g4) {
    const float* d = (const float*)(sm + base) + u;
#pragma unroll
    for (int gate = 0; gate < 4; gate++) {
        float v = d[((0*4 + gate)*16 + row) * 32];
        v += d[((1*4 + gate)*16 + row) * 32];
        v += d[((2*4 + gate)*16 + row) * 32];
        v += d[((3*4 + gate)*16 + row) * 32];
        g4[gate] = v;
    }
}

__global__ void __launch_bounds__(1024, 1) __cluster_dims__(4, 1, 1)
lstm_main(const float* __restrict__ x, const float* __restrict__ out_b,
          float* __restrict__ out)
{
    extern __shared__ __align__(16) char sm[];
    const int tid = threadIdx.x;
    const int u = tid & 31, wid = tid >> 5;        // 32 warps
    const int s = wid & 3, rp = wid >> 2;          // k-quarter, row-pair 0..7
    const bool epi = (tid < 512);
    const int row = wid;                           // valid for epi threads (0..15)
    const int p  = blockIdx.x & 3;
    const int bg = (blockIdx.x >> 2) * 16;
    const u32 hb = epi ? hboff(row, p*32 + u) : 0u;

    u32 sb = (u32)__cvta_generic_to_shared(sm);
    u32 dsm[4];
#pragma unroll
    for (int r = 0; r < 4; r++)
        asm("mapa.shared::cluster.u32 %0, %1, %2;" : "=r"(dsm[r]) : "r"(sb), "r"(r));

    stage_w(sm, 0, p, tid);
    stage_w(sm, 1, p, tid);
#pragma unroll
    for (int i = 0; i < 2; i++)                    // zero SX,SH0,SH1,SOW (32KB)
        ((uint4*)(sm + SX))[tid + i*1024] = make_uint4(0,0,0,0);
    __syncthreads();
    if (tid < 256) {
        const int xr = tid >> 4, oct = tid & 15;
        const float* xp = x + ((size_t)(bg + xr) * TT) * 128 + oct * 8;
        float4 a = *(const float4*)xp, b = *(const float4*)(xp + 4);
        u32* X = (u32*)(sm + SX);
        X[xh_word(oct*4+0, xr)] = pk(a.x, a.y);
        X[xh_word(oct*4+1, xr)] = pk(a.z, a.w);
        X[xh_word(oct*4+2, xr)] = pk(b.x, b.y);
        X[xh_word(oct*4+3, xr)] = pk(b.z, b.w);
    }
    float bi0[4], bi1[4];
    if (epi) {
#pragma unroll
        for (int g = 0; g < 4; g++) {
            bi0[g] = g_b[0][g*128 + p*32 + u];
            bi1[g] = g_b[1][g*128 + p*32 + u];
        }
    }
    float c0 = 0.f, c1 = 0.f;
    float g8[8], g4[4];
    __syncthreads();
    CBAR();

    // -------------------- encoder: 1 CBAR / step --------------------
    for (int t = 0; t < TT; t++) {
        const u32 pt = (u32)(t & 1) * 4096u, pn = pt ^ 4096u;
        float4 xa, xb;
        const bool pre = (tid < 256) && (t < TT - 1);
        if (pre) {
            const float* xp = x + ((size_t)(bg + (tid >> 4)) * TT + t + 1) * 128 + (tid & 15) * 8;
            xa = *(const float4*)xp; xb = *(const float4*)(xp + 4);
        }
        gemm_r2(sm, SW0I, SW0H, SX + pt, SH0 + pt, u, rp, s, g8);
        red_store(sm, SRED0, u, rp, s, g8);
        __syncthreads();
        if (epi) {
            red_gates(sm, SRED0, u, row, g4);
            float cn = sigf(g4[1] + bi0[1]) * c0 + sigf(g4[0] + bi0[0]) * tanhfa(g4[2] + bi0[2]);
            c0 = cn;
            float h = sigf(g4[3] + bi0[3]) * tanhfa(cn);
            bc4(dsm, SH0 + pn + hb, __half_as_ushort(__float2half(h)));
        }
        if (pre) {
            const int xr = tid >> 4, oct = tid & 15;
            u32* X = (u32*)(sm + SX + pn);
            X[xh_word(oct*4+0, xr)] = pk(xa.x, xa.y);
            X[xh_word(oct*4+1, xr)] = pk(xa.z, xa.w);
            X[xh_word(oct*4+2, xr)] = pk(xb.x, xb.y);
            X[xh_word(oct*4+3, xr)] = pk(xb.z, xb.w);
        }
        CBAR();
        gemm_r2(sm, SW1I, SW1H, SH0 + pn, SH1 + pt, u, rp, s, g8);
        red_store(sm, SRED1, u, rp, s, g8);
        __syncthreads();
        if (epi) {
            red_gates(sm, SRED1, u, row, g4);
            float cn = sigf(g4[1] + bi1[1]) * c1 + sigf(g4[0] + bi1[0]) * tanhfa(g4[2] + bi1[2]);
            c1 = cn;
            float h = sigf(g4[3] + bi1[3]) * tanhfa(cn);
            bc4(dsm, SH1 + pn + hb, __half_as_ushort(__float2half(h)));
        }
        // SH1+pn consumed only after next step's CBAR
    }

    // -------------------- switch --------------------
    CBAR();
    if (tid < 256) {
        uint4 x0v = ((uint4*)(sm + SH1))[tid];         // final h1 (parity 0)
        ((uint4*)(sm + SX))[tid]  = x0v;
        ((uint4*)(sm + SH0))[tid] = make_uint4(0,0,0,0);
        ((uint4*)(sm + SH1))[tid] = make_uint4(0,0,0,0);
    }
    stage_w(sm, 2, p, tid);
    stage_w(sm, 3, p, tid);
    if (tid < 512)
        ((uint4*)(sm + SOW))[tid] = ((const uint4*)g_OWp)[p * 512 + tid];
    if (epi) {
#pragma unroll
        for (int g = 0; g < 4; g++) {
            bi0[g] = g_b[2][g*128 + p*32 + u];
            bi1[g] = g_b[3][g*128 + p*32 + u];
        }
    }
    const float obv = out_b[p * 32 + u];
    c0 = 0.f; c1 = 0.f;
    __syncthreads();

    // -------------------- decoder: 2 CBARs / step --------------------
    const u32 pbase = (u32)((row >> 1) * 128 + (row & 1) * 4);
    for (int t = 0; t < TT; t++) {
        const u32 pt = (u32)(t & 1) * 4096u, pn = pt ^ 4096u;
        gemm_r2(sm, SW0I, SW0H, SX + pt, SH0 + pt, u, rp, s, g8);
        red_store(sm, SRED0, u, rp, s, g8);
        __syncthreads();
        if (epi) {
            red_gates(sm, SRED0, u, row, g4);
            float cn = sigf(g4[1] + bi0[1]) * c0 + sigf(g4[0] + bi0[0]) * tanhfa(g4[2] + bi0[2]);
            c0 = cn;
            float h = sigf(g4[3] + bi0[3]) * tanhfa(cn);
            bc4(dsm, SH0 + pn + hb, __half_as_ushort(__float2half(h)));
        }
        CBAR();
        gemm_r2(sm, SW1I, SW1H, SH0 + pn, SH1 + pt, u, rp, s, g8);
        red_store(sm, SRED1, u, rp, s, g8);
        __syncthreads();
        if (epi) {
            red_gates(sm, SRED1, u, row, g4);
            float cn = sigf(g4[1] + bi1[1]) * c1 + sigf(g4[0] + bi1[0]) * tanhfa(g4[2] + bi1[2]);
            c1 = cn;
            float h = sigf(g4[3] + bi1[3]) * tanhfa(cn);
            u16 hu = __half_as_ushort(__float2half(h));
            bc4(dsm, SH1 + pn + hb, hu);
            bc4(dsm, SX  + pn + hb, hu);
        }
        CBAR();
        if (epi) {   // projection: thread -> (row, dim p*32+u)
            u64 P = 0;
            __half2 pa = __float2half2_rn(0.f);
            const char* hx = sm + SX + pn + pbase;
            const __half2* ow = (const __half2*)(sm + SOW) + u;
#pragma unroll 4
            for (int kk = 0; kk < 64; kk++) {
                __half2 hv = *(const __half2*)(hx + (kk >> 4)*1024 + (kk & 15)*8);
                pa = __hfma2(ow[kk*32], hv, pa);
                if ((kk & 15) == 15) { spill(P, pa); pa = __float2half2_rn(0.f); }
            }
            out[((size_t)(bg + row) * TT + t) * 128 + p * 32 + u] = fin2(P) + obv;
        }
    }
}

extern "C" void kernel_launch(void* const* d_in, const int* in_sizes, int n_in,
                              void* d_out, int out_size)
{
    cudaFuncSetAttribute(lstm_main, cudaFuncAttributeMaxDynamicSharedMemorySize, STOT);
    prep_kernel<<<512, 512>>>(
        (const float*)d_in[1],  (const float*)d_in[2],  (const float*)d_in[3],
        (const float*)d_in[4],  (const float*)d_in[5],  (const float*)d_in[6],
        (const float*)d_in[7],  (const float*)d_in[8],  (const float*)d_in[9],
        (const float*)d_in[10], (const float*)d_in[11], (const float*)d_in[12],
        (const float*)d_in[13], (const float*)d_in[14], (const float*)d_in[15],
        (const float*)d_in[16], (const float*)d_in[17]);
    lstm_main<<<128, 1024, STOT>>>((const float*)d_in[0], (const float*)d_in[18],
                                   (float*)d_out);
}